// round 13
// baseline (speedup 1.0000x reference)
#include <cuda_runtime.h>
#include <cstdint>

// Multi-scale deformable attention, nearest sampling, zero padding.
//   value: (6, 14960, 8, 32) f32   loc: (6, 40000, 8, 4, 4, 2) f32
//   out:   (6, 40000, 256) f32
//
// Block = 4 queries, 256 threads.
// Phase 1 (paired): thread t handles 2 consecutive points (same level) of one
//          (q,h): one float4 loc load, shared level constants, one STS.64 of
//          two int offsets (float4-element index key<<6, or -1 if invalid).
// Phase 2: warp = (query, 4 heads); 16 independent iterations of
//          LDS.32 (offset broadcast per 8-lane group, conflict-free 80B row
//          stride) + predicated LDG.128 + predicated 4x FADD.
//          Levels 0-1 (p<8) loaded evict-first (__ldcs) to keep levels 2-3
//          L1-resident. Full-warp STG.128 (streaming) writes 4 heads x 128B.

#define BS        6
#define NQ        40000
#define NHEADS    8
#define NKEYS     14960
#define QPB       4            // queries per block

__global__ __launch_bounds__(256, 8)
void msda_kernel(const float* __restrict__ value,
                 const float* __restrict__ loc,
                 float* __restrict__ out)
{
    // Row per (qi,h): 16 int offsets + 4 pad = 20 ints = 80 bytes.
    // 80B stride: phase-2 4-group LDS.32 broadcast hits banks p+{0,20,8,28}
    // (distinct) -> conflict-free.
    __shared__ int skey[QPB * NHEADS * 20];

    const int tid = threadIdx.x;
    const int b   = blockIdx.y;
    const int q0  = blockIdx.x * QPB;

    // ---------------- Phase 1: 256 threads x 1 point-pair ----------------
    {
        const int qi = tid >> 6;          // query in block
        const int h  = (tid >> 3) & 7;    // head
        const int pp = tid & 7;           // point pair (points 2pp, 2pp+1)
        const int l  = pp >> 1;           // level (pairs never straddle levels)

        const int W  = 176 >> l;
        const int Hh = 64  >> l;
        // level offsets 0, 11264, 14080, 14784 (geometric /4 partial sums)
        const int base = (45056 - (45056 >> (2 * l))) / 3;

        const unsigned loc4 = ((unsigned)(b * NQ + q0 + qi) * NHEADS + h) * 8 + pp;
        const float4 s = __ldcs(reinterpret_cast<const float4*>(loc) + loc4);

        // Replicate reference arithmetic exactly (no fma contraction):
        // g = 2*s - 1 ; x = ((g + 1) * w) * 0.5 - 0.5 ; ix = rint(x)
        const float fW = (float)W, fH = (float)Hh;

        float gx0 = __fadd_rn(__fmul_rn(2.0f, s.x), -1.0f);
        float gy0 = __fadd_rn(__fmul_rn(2.0f, s.y), -1.0f);
        float x0  = __fadd_rn(__fmul_rn(__fmul_rn(__fadd_rn(gx0, 1.0f), fW), 0.5f), -0.5f);
        float y0  = __fadd_rn(__fmul_rn(__fmul_rn(__fadd_rn(gy0, 1.0f), fH), 0.5f), -0.5f);
        const int ix0 = __float2int_rn(x0);
        const int iy0 = __float2int_rn(y0);

        float gx1 = __fadd_rn(__fmul_rn(2.0f, s.z), -1.0f);
        float gy1 = __fadd_rn(__fmul_rn(2.0f, s.w), -1.0f);
        float x1  = __fadd_rn(__fmul_rn(__fmul_rn(__fadd_rn(gx1, 1.0f), fW), 0.5f), -0.5f);
        float y1  = __fadd_rn(__fmul_rn(__fmul_rn(__fadd_rn(gy1, 1.0f), fH), 0.5f), -0.5f);
        const int ix1 = __float2int_rn(x1);
        const int iy1 = __float2int_rn(y1);

        const bool v0 = ((unsigned)ix0 < (unsigned)W) & ((unsigned)iy0 < (unsigned)Hh);
        const bool v1 = ((unsigned)ix1 < (unsigned)W) & ((unsigned)iy1 < (unsigned)Hh);

        const int k0 = base + min(max(iy0, 0), Hh - 1) * W + min(max(ix0, 0), W - 1);
        const int k1 = base + min(max(iy1, 0), Hh - 1) * W + min(max(ix1, 0), W - 1);

        // float4-element offset of the key's 1KB line (64 float4s), -1 = skip.
        reinterpret_cast<int2*>(skey)[(qi * NHEADS + h) * 10 + pp] =
            make_int2(v0 ? (k0 << 6) : -1,
                      v1 ? (k1 << 6) : -1);
    }

    __syncthreads();

    // ---------------- Phase 2: gather (warp = one query, 4 heads) ----------
    const int w     = tid >> 5;          // 0..7
    const int lane  = tid & 31;
    const int qi    = w >> 1;
    const int hbase = (w & 1) << 2;
    const int g     = lane >> 3;         // head group within warp
    const int h     = hbase + g;
    const int d4    = lane & 7;          // float4 slot within the 128B line

    const int q = q0 + qi;

    // value[b, key, h, :] in float4 units; km is key<<6.
    const float4* vp4 = reinterpret_cast<const float4*>(value)
                      + (size_t)b * ((size_t)NKEYS * 64) + (h << 3) + d4;
    const int* kp = &skey[(qi * NHEADS + h) * 20];

    float4 acc = make_float4(0.f, 0.f, 0.f, 0.f);
#pragma unroll
    for (int p = 0; p < 16; ++p) {
        const int km = kp[p];                                    // LDS.32, imm offset
        if (km >= 0) {
            // Levels 0-1: huge footprint, evict-first so levels 2-3 stay in L1.
            const float4 v = (p < 8) ? __ldcs(vp4 + km) : __ldg(vp4 + km);
            acc.x += v.x;
            acc.y += v.y;
            acc.z += v.z;
            acc.w += v.w;
        }
    }

    // Full-warp 512B streaming store: 4 heads x 128B for this query.
    float4* op4 = reinterpret_cast<float4*>(out)
                + (((size_t)b * NQ + q) << 6) + (hbase << 3) + lane;
    __stcs(op4, acc);
}

extern "C" void kernel_launch(void* const* d_in, const int* in_sizes, int n_in,
                              void* d_out, int out_size)
{
    const float* value = (const float*)d_in[0];
    // d_in[1] = value_spatial_shapes (constants, folded into the kernel)
    const float* loc   = (const float*)d_in[2];
    float* out         = (float*)d_out;

    dim3 grid(NQ / QPB, BS);
    msda_kernel<<<grid, 256>>>(value, loc, out);
}